// round 2
// baseline (speedup 1.0000x reference)
#include <cuda_runtime.h>
#include <math.h>

// Problem constants
#define BB 256      // batch
#define TT 128      // time steps
#define EMBED 256
#define HIDDEN 512
#define VOCAB 1004
#define FC_IN 2048
#define GATES 2048  // 4*HIDDEN

// -------------------- device scratch (no allocation allowed) --------------------
__device__ float g_feats[BB * EMBED];                    // [256,256]
__device__ float g_base_att[BB * EMBED];                 // feats@W_attFᵀ + b_att
__device__ float g_base_ih[BB * GATES];                  // feats@W_ihFᵀ + b_ih + b_hh
__device__ float g_bsum[GATES];                          // b_ih + b_hh
__device__ float g_ctx[(size_t)BB * TT * EMBED];         // 32 MB
__device__ float g_gin[(size_t)BB * TT * GATES];         // 256 MB  [B,T,2048]
__device__ float g_hs[(size_t)BB * TT * HIDDEN];         // 64 MB   [B,T,512]
__device__ float g_h[BB * HIDDEN];
__device__ float g_c[BB * HIDDEN];
__device__ float g_gates[BB * GATES];                    // per-step h@W_hhᵀ

// -------------------- generic C = A @ Bᵀ (+bias) (+row-broadcast Cadd) --------------------
// A: [M,K] row-major with row stride lda; Bw: [N,K] row-major with row stride ldb.
// Requires: M % BM == 0, K % BK == 0, all row strides % 4 == 0, 16B-aligned pointers.
// N may be arbitrary (guarded).
template <int BM, int BN, int BK, int TM, int TN>
__global__ void gemm_abt(const float* __restrict__ A, int lda,
                         const float* __restrict__ Bw, int ldb,
                         const float* __restrict__ bias,
                         const float* __restrict__ Cadd, int rowdiv,
                         float* __restrict__ C,
                         int M, int N, int K) {
    constexpr int THREADS = (BM / TM) * (BN / TN);
    constexpr int KV = BK / 4;                 // float4 chunks per K-tile row
    constexpr int ROWS_PER_PASS = THREADS / KV;

    __shared__ float As[BK][BM];
    __shared__ float Bs[BK][BN];

    const int tid = threadIdx.x;
    const int block_m = blockIdx.y * BM;
    const int block_n = blockIdx.x * BN;

    const int aRow = tid / KV;
    const int aCol = (tid % KV) * 4;

    const int tcol = tid % (BN / TN);
    const int trow = tid / (BN / TN);

    float acc[TM][TN];
#pragma unroll
    for (int i = 0; i < TM; i++)
#pragma unroll
        for (int j = 0; j < TN; j++) acc[i][j] = 0.f;

    float regM[TM], regN[TN];

    for (int kt = 0; kt < K; kt += BK) {
        // load A tile (transposed into As[k][m])
#pragma unroll
        for (int rr = 0; rr < BM; rr += ROWS_PER_PASS) {
            int r = rr + aRow;
            size_t gidx = (size_t)(block_m + r) * lda + kt + aCol;
            float4 v = *(const float4*)(A + gidx);
            As[aCol + 0][r] = v.x;
            As[aCol + 1][r] = v.y;
            As[aCol + 2][r] = v.z;
            As[aCol + 3][r] = v.w;
        }
        // load B tile (transposed into Bs[k][n]), guard n < N
#pragma unroll
        for (int rr = 0; rr < BN; rr += ROWS_PER_PASS) {
            int r = rr + aRow;
            int gn = block_n + r;
            float4 v = make_float4(0.f, 0.f, 0.f, 0.f);
            if (gn < N) {
                size_t gidx = (size_t)gn * ldb + kt + aCol;
                v = *(const float4*)(Bw + gidx);
            }
            Bs[aCol + 0][r] = v.x;
            Bs[aCol + 1][r] = v.y;
            Bs[aCol + 2][r] = v.z;
            Bs[aCol + 3][r] = v.w;
        }
        __syncthreads();

#pragma unroll
        for (int k = 0; k < BK; k++) {
#pragma unroll
            for (int i = 0; i < TM; i++) regM[i] = As[k][trow * TM + i];
#pragma unroll
            for (int j = 0; j < TN; j++) regN[j] = Bs[k][tcol * TN + j];
#pragma unroll
            for (int i = 0; i < TM; i++)
#pragma unroll
                for (int j = 0; j < TN; j++) acc[i][j] += regM[i] * regN[j];
        }
        __syncthreads();
    }

    // epilogue
#pragma unroll
    for (int i = 0; i < TM; i++) {
        int gm = block_m + trow * TM + i;
        const float* caddrow = nullptr;
        if (Cadd) caddrow = Cadd + (size_t)(rowdiv > 1 ? gm / rowdiv : gm) * N;
#pragma unroll
        for (int j = 0; j < TN; j++) {
            int gn = block_n + tcol * TN + j;
            if (gn < N) {
                float v = acc[i][j];
                if (bias) v += bias[gn];
                if (caddrow) v += caddrow[gn];
                C[(size_t)gm * N + gn] = v;
            }
        }
    }
}

// -------------------- small elementwise kernels --------------------
__global__ void bias_sum_kernel(const float* __restrict__ b_ih,
                                const float* __restrict__ b_hh,
                                float* __restrict__ bsum) {
    int n = blockIdx.x * blockDim.x + threadIdx.x;
    if (n < GATES) bsum[n] = b_ih[n] + b_hh[n];
}

__device__ __forceinline__ float sigmoidf_(float x) {
    return 1.f / (1.f + expf(-x));
}

// gates_total = gatesHH (h@W_hhᵀ, zero at t=0) + gin[:, t, :]; apply LSTM cell.
__global__ void lstm_cell_kernel(const float* __restrict__ gatesHH,
                                 const float* __restrict__ gin,
                                 float* __restrict__ h,
                                 float* __restrict__ c,
                                 float* __restrict__ hs,
                                 int t) {
    int idx = blockIdx.x * blockDim.x + threadIdx.x;  // 0 .. B*HIDDEN-1
    if (idx >= BB * HIDDEN) return;
    int b = idx / HIDDEN;
    int j = idx - b * HIDDEN;

    const float* grow = gin + ((size_t)b * TT + t) * GATES;
    float i_, f_, g_, o_;
    if (t == 0) {
        i_ = grow[j];
        f_ = grow[HIDDEN + j];
        g_ = grow[2 * HIDDEN + j];
        o_ = grow[3 * HIDDEN + j];
    } else {
        const float* ghh = gatesHH + (size_t)b * GATES;
        i_ = ghh[j] + grow[j];
        f_ = ghh[HIDDEN + j] + grow[HIDDEN + j];
        g_ = ghh[2 * HIDDEN + j] + grow[2 * HIDDEN + j];
        o_ = ghh[3 * HIDDEN + j] + grow[3 * HIDDEN + j];
    }

    float cprev = (t == 0) ? 0.f : c[idx];
    float cc = sigmoidf_(f_) * cprev + sigmoidf_(i_) * tanhf(g_);
    float hh = sigmoidf_(o_) * tanhf(cc);
    c[idx] = cc;
    h[idx] = hh;
    hs[((size_t)b * TT + t) * HIDDEN + j] = hh;
}

// -------------------- launch --------------------
extern "C" void kernel_launch(void* const* d_in, const int* in_sizes, int n_in,
                              void* d_out, int out_size) {
    const float* images   = (const float*)d_in[0];   // [256, 2048]
    const float* captions = (const float*)d_in[1];   // [256, 128, 512]
    const float* W_fc     = (const float*)d_in[2];   // [256, 2048]
    const float* b_fc     = (const float*)d_in[3];   // [256]
    const float* W_att    = (const float*)d_in[4];   // [256, 768]
    const float* b_att    = (const float*)d_in[5];   // [256]
    const float* W_ih     = (const float*)d_in[6];   // [2048, 512]
    const float* b_ih     = (const float*)d_in[7];   // [2048]
    const float* W_hh     = (const float*)d_in[8];   // [2048, 512]
    const float* b_hh     = (const float*)d_in[9];   // [2048]
    const float* W_out    = (const float*)d_in[10];  // [1004, 512]
    const float* b_out    = (const float*)d_in[11];  // [1004]
    float* out = (float*)d_out;                      // [256, 128, 1004]

    static float *p_feats = nullptr, *p_batt = nullptr, *p_bih = nullptr,
                 *p_bsum = nullptr, *p_ctx = nullptr, *p_gin = nullptr,
                 *p_hs = nullptr, *p_h = nullptr, *p_c = nullptr, *p_gates = nullptr;
    if (!p_feats) {
        cudaGetSymbolAddress((void**)&p_feats, g_feats);
        cudaGetSymbolAddress((void**)&p_batt, g_base_att);
        cudaGetSymbolAddress((void**)&p_bih, g_base_ih);
        cudaGetSymbolAddress((void**)&p_bsum, g_bsum);
        cudaGetSymbolAddress((void**)&p_ctx, g_ctx);
        cudaGetSymbolAddress((void**)&p_gin, g_gin);
        cudaGetSymbolAddress((void**)&p_hs, g_hs);
        cudaGetSymbolAddress((void**)&p_h, g_h);
        cudaGetSymbolAddress((void**)&p_c, g_c);
        cudaGetSymbolAddress((void**)&p_gates, g_gates);
    }

    auto big = [&](const float* A, int lda, const float* Bw, int ldb,
                   const float* bias, const float* Cadd, int rowdiv,
                   float* C, int M, int N, int K) {
        dim3 grid((N + 127) / 128, M / 128);
        gemm_abt<128, 128, 16, 8, 8><<<grid, 256>>>(A, lda, Bw, ldb, bias, Cadd,
                                                    rowdiv, C, M, N, K);
    };
    auto small = [&](const float* A, int lda, const float* Bw, int ldb,
                     const float* bias, const float* Cadd, int rowdiv,
                     float* C, int M, int N, int K) {
        dim3 grid((N + 63) / 64, M / 64);
        gemm_abt<64, 64, 16, 4, 4><<<grid, 256>>>(A, lda, Bw, ldb, bias, Cadd,
                                                  rowdiv, C, M, N, K);
    };

    // b_ih + b_hh
    bias_sum_kernel<<<(GATES + 255) / 256, 256>>>(b_ih, b_hh, p_bsum);

    // feats = images @ W_fcᵀ + b_fc                [256,256] K=2048
    big(images, FC_IN, W_fc, FC_IN, b_fc, nullptr, 0, p_feats, BB, EMBED, FC_IN);

    // base_att = feats @ W_att[:, :256]ᵀ + b_att   [256,256] K=256
    small(p_feats, EMBED, W_att, HIDDEN + EMBED, b_att, nullptr, 0,
          p_batt, BB, EMBED, EMBED);

    // base_ih = feats @ W_ih[:, :256]ᵀ + (b_ih+b_hh)  [256,2048] K=256
    small(p_feats, EMBED, W_ih, 2 * EMBED, p_bsum, nullptr, 0,
          p_bih, BB, GATES, EMBED);

    // ctx[b*T+t] = captions[b,t] @ W_att[:, 256:]ᵀ + base_att[b]   [32768,256] K=512
    big(captions, HIDDEN, W_att + EMBED, HIDDEN + EMBED, nullptr, p_batt, TT,
        p_ctx, BB * TT, EMBED, HIDDEN);

    // gin[b*T+t] = ctx[b*T+t] @ W_ih[:, 256:]ᵀ + base_ih[b]        [32768,2048] K=256
    big(p_ctx, EMBED, W_ih + EMBED, 2 * EMBED, nullptr, p_bih, TT,
        p_gin, BB * TT, GATES, EMBED);

    // recurrence
    for (int t = 0; t < TT; t++) {
        if (t > 0) {
            // gatesHH = h @ W_hhᵀ    [256,2048] K=512
            small(p_h, HIDDEN, W_hh, HIDDEN, nullptr, nullptr, 0,
                  p_gates, BB, GATES, HIDDEN);
        }
        lstm_cell_kernel<<<(BB * HIDDEN + 255) / 256, 256>>>(
            p_gates, p_gin, p_h, p_c, p_hs, t);
    }

    // out = hs @ W_outᵀ + b_out     [32768,1004] K=512
    big(p_hs, HIDDEN, W_out, HIDDEN, b_out, nullptr, 0,
        out, BB * TT, VOCAB, HIDDEN);
}

// round 3
// speedup vs baseline: 1.7615x; 1.7615x over previous
#include <cuda_runtime.h>
#include <math.h>

// Problem constants
#define BB 256      // batch
#define TT 128      // time steps
#define EMBED 256
#define HIDDEN 512
#define VOCAB 1004
#define FC_IN 2048
#define GATES 2048  // 4*HIDDEN

#define NCTA 128    // persistent recurrence grid

// -------------------- device scratch (no allocation allowed) --------------------
__device__ float g_feats[BB * EMBED];                    // [256,256]
__device__ float g_base_att[BB * EMBED];                 // feats@W_attFᵀ + b_att
__device__ float g_base_ih[BB * GATES];                  // feats@W_ihFᵀ + b_ih + b_hh
__device__ float g_bsum[GATES];                          // b_ih + b_hh
__device__ float g_ctx[(size_t)BB * TT * EMBED];         // 32 MB
__device__ float g_gin[(size_t)BB * TT * GATES];         // 256 MB  [B,T,2048]
__device__ float g_hs[(size_t)BB * TT * HIDDEN];         // 64 MB   [B,T,512]
__device__ float g_hbuf[2][BB][HIDDEN];                  // double-buffered h
__device__ unsigned g_count;                             // barrier arrivals (monotonic)
__device__ unsigned g_epoch;                             // barrier release epoch

// -------------------- generic C = A @ Bᵀ (+bias) (+row-broadcast Cadd) --------------------
// A: [M,K] row-major with row stride lda; Bw: [N,K] row-major with row stride ldb.
// Requires: M % BM == 0, K % BK == 0, all row strides % 4 == 0, 16B-aligned pointers.
// N may be arbitrary (guarded).
template <int BM, int BN, int BK, int TM, int TN>
__global__ void gemm_abt(const float* __restrict__ A, int lda,
                         const float* __restrict__ Bw, int ldb,
                         const float* __restrict__ bias,
                         const float* __restrict__ Cadd, int rowdiv,
                         float* __restrict__ C,
                         int M, int N, int K) {
    constexpr int THREADS = (BM / TM) * (BN / TN);
    constexpr int KV = BK / 4;                 // float4 chunks per K-tile row
    constexpr int ROWS_PER_PASS = THREADS / KV;

    __shared__ float As[BK][BM];
    __shared__ float Bs[BK][BN];

    const int tid = threadIdx.x;
    const int block_m = blockIdx.y * BM;
    const int block_n = blockIdx.x * BN;

    const int aRow = tid / KV;
    const int aCol = (tid % KV) * 4;

    const int tcol = tid % (BN / TN);
    const int trow = tid / (BN / TN);

    float acc[TM][TN];
#pragma unroll
    for (int i = 0; i < TM; i++)
#pragma unroll
        for (int j = 0; j < TN; j++) acc[i][j] = 0.f;

    float regM[TM], regN[TN];

    for (int kt = 0; kt < K; kt += BK) {
        // load A tile (transposed into As[k][m])
#pragma unroll
        for (int rr = 0; rr < BM; rr += ROWS_PER_PASS) {
            int r = rr + aRow;
            size_t gidx = (size_t)(block_m + r) * lda + kt + aCol;
            float4 v = *(const float4*)(A + gidx);
            As[aCol + 0][r] = v.x;
            As[aCol + 1][r] = v.y;
            As[aCol + 2][r] = v.z;
            As[aCol + 3][r] = v.w;
        }
        // load B tile (transposed into Bs[k][n]), guard n < N
#pragma unroll
        for (int rr = 0; rr < BN; rr += ROWS_PER_PASS) {
            int r = rr + aRow;
            int gn = block_n + r;
            float4 v = make_float4(0.f, 0.f, 0.f, 0.f);
            if (gn < N) {
                size_t gidx = (size_t)gn * ldb + kt + aCol;
                v = *(const float4*)(Bw + gidx);
            }
            Bs[aCol + 0][r] = v.x;
            Bs[aCol + 1][r] = v.y;
            Bs[aCol + 2][r] = v.z;
            Bs[aCol + 3][r] = v.w;
        }
        __syncthreads();

#pragma unroll
        for (int k = 0; k < BK; k++) {
#pragma unroll
            for (int i = 0; i < TM; i++) regM[i] = As[k][trow * TM + i];
#pragma unroll
            for (int j = 0; j < TN; j++) regN[j] = Bs[k][tcol * TN + j];
#pragma unroll
            for (int i = 0; i < TM; i++)
#pragma unroll
                for (int j = 0; j < TN; j++) acc[i][j] += regM[i] * regN[j];
        }
        __syncthreads();
    }

    // epilogue
#pragma unroll
    for (int i = 0; i < TM; i++) {
        int gm = block_m + trow * TM + i;
        const float* caddrow = nullptr;
        if (Cadd) caddrow = Cadd + (size_t)(rowdiv > 1 ? gm / rowdiv : gm) * N;
#pragma unroll
        for (int j = 0; j < TN; j++) {
            int gn = block_n + tcol * TN + j;
            if (gn < N) {
                float v = acc[i][j];
                if (bias) v += bias[gn];
                if (caddrow) v += caddrow[gn];
                C[(size_t)gm * N + gn] = v;
            }
        }
    }
}

// -------------------- init kernel: bias sum + barrier reset --------------------
__global__ void init_kernel(const float* __restrict__ b_ih,
                            const float* __restrict__ b_hh,
                            float* __restrict__ bsum) {
    int n = blockIdx.x * blockDim.x + threadIdx.x;
    if (n < GATES) bsum[n] = b_ih[n] + b_hh[n];
    if (n == 0) { g_count = 0u; g_epoch = 0u; }
}

__device__ __forceinline__ float sigmoidf_(float x) {
    return 1.f / (1.f + expf(-x));
}

// -------------------- persistent recurrence kernel --------------------
// Grid: 128 CTAs x 256 threads. CTA (bid): batch half bbase = (bid&1)*128,
// hidden-index group jbase = (bid>>1)*8. CTA computes gate columns
// {g*512 + jbase + jj : g in 0..3, jj in 0..7} for its 128 batches, so the
// LSTM cell is fully CTA-local. One grid barrier per step (h double-buffered).
//
// SMEM layout (dynamic):
//   Ws [512][36]  : cached W_hh slice, k-major, padded stride 36 (73728 B)
//   Hs [16][128]  : staged h K-tile, k-major                      (8192 B)
//   Gs [128][33]  : gate values for cell, padded                  (16896 B)
//   Cs [128*8]    : persistent c-state slice                      (4096 B)
#define SM_WS   (512 * 36)
#define SM_HS   (16 * 128)
#define SM_GS   (128 * 33)
#define SM_CS   (128 * 8)
#define SM_TOTAL_BYTES ((SM_WS + SM_HS + SM_GS + SM_CS) * 4)

__global__ void __launch_bounds__(256, 1)
lstm_persistent(const float* __restrict__ W_hh,   // [2048,512]
                const float* __restrict__ gin,    // [B,T,2048]
                float* __restrict__ hs)           // [B,T,512]
{
    extern __shared__ float sm[];
    float* Ws = sm;
    float* Hs = Ws + SM_WS;
    float* Gs = Hs + SM_HS;
    float* Cs = Gs + SM_GS;

    const int tid = threadIdx.x;
    const int bid = blockIdx.x;
    const int bbase = (bid & 1) * 128;
    const int jbase = (bid >> 1) * 8;

    // ---- cache W_hh slice (once) ----
    // local col c = gate*8 + jj  ->  global row gcol = gate*512 + jbase + jj
    for (int idx = tid; idx < 32 * 512; idx += 256) {
        int c = idx >> 9;          // 0..31  (slow: each col read coalesced in k)
        int k = idx & 511;
        int gcol = (c >> 3) * 512 + jbase + (c & 7);
        Ws[k * 36 + c] = W_hh[(size_t)gcol * HIDDEN + k];
    }
    __syncthreads();

    const int trow = tid >> 3;   // 0..31 -> batch sub-rows trow*4..+3
    const int tcol = tid & 7;    // 0..7  -> cols tcol*4..+3

    unsigned epoch = 0;

    for (int t = 0; t < TT; t++) {
        float acc[4][4];
#pragma unroll
        for (int i = 0; i < 4; i++)
#pragma unroll
            for (int j = 0; j < 4; j++) acc[i][j] = 0.f;

        if (t > 0) {
            const float* hsrc = &g_hbuf[(t - 1) & 1][bbase][0];
            for (int kt = 0; kt < HIDDEN; kt += 16) {
                // stage Hs[16][128] (transposed)
#pragma unroll
                for (int s = 0; s < 2; s++) {
                    int idx = tid * 2 + s;      // 0..511 over [128 rows][4 f4]
                    int r = idx >> 2;
                    int q = idx & 3;
                    float4 v = *(const float4*)(hsrc + (size_t)r * HIDDEN + kt + q * 4);
                    Hs[(q * 4 + 0) * 128 + r] = v.x;
                    Hs[(q * 4 + 1) * 128 + r] = v.y;
                    Hs[(q * 4 + 2) * 128 + r] = v.z;
                    Hs[(q * 4 + 3) * 128 + r] = v.w;
                }
                __syncthreads();
#pragma unroll
                for (int k = 0; k < 16; k++) {
                    float4 m = *(const float4*)(Hs + k * 128 + trow * 4);
                    float4 n = *(const float4*)(Ws + (kt + k) * 36 + tcol * 4);
                    float rm[4] = {m.x, m.y, m.z, m.w};
                    float rn[4] = {n.x, n.y, n.z, n.w};
#pragma unroll
                    for (int i = 0; i < 4; i++)
#pragma unroll
                        for (int j = 0; j < 4; j++) acc[i][j] += rm[i] * rn[j];
                }
                __syncthreads();
            }
        }

        // ---- add gin, stage gates in SMEM ----
        {
            int c0 = tcol * 4;                   // 4-aligned -> same gate group
            int gate = c0 >> 3;
            int jj0 = c0 & 7;
#pragma unroll
            for (int i = 0; i < 4; i++) {
                int bl = trow * 4 + i;
                const float* grow_p =
                    gin + ((size_t)(bbase + bl) * TT + t) * GATES + gate * 512 + jbase + jj0;
                float4 g4 = *(const float4*)grow_p;
                Gs[bl * 33 + c0 + 0] = acc[i][0] + g4.x;
                Gs[bl * 33 + c0 + 1] = acc[i][1] + g4.y;
                Gs[bl * 33 + c0 + 2] = acc[i][2] + g4.z;
                Gs[bl * 33 + c0 + 3] = acc[i][3] + g4.w;
            }
        }
        __syncthreads();

        // ---- LSTM cell (CTA-local), write h + hs ----
#pragma unroll
        for (int s = 0; s < 4; s++) {
            int q = tid * 4 + s;                 // 0..1023
            int bl = q >> 3;
            int jj = q & 7;
            float gi = Gs[bl * 33 + jj];
            float gf = Gs[bl * 33 + 8 + jj];
            float gg = Gs[bl * 33 + 16 + jj];
            float go = Gs[bl * 33 + 24 + jj];
            float cprev = (t == 0) ? 0.f : Cs[bl * 8 + jj];
            float cc = sigmoidf_(gf) * cprev + sigmoidf_(gi) * tanhf(gg);
            float hh = sigmoidf_(go) * tanhf(cc);
            Cs[bl * 8 + jj] = cc;
            g_hbuf[t & 1][bbase + bl][jbase + jj] = hh;
            hs[((size_t)(bbase + bl) * TT + t) * HIDDEN + jbase + jj] = hh;
        }

        // ---- grid barrier (monotonic, no reset) ----
        if (t < TT - 1) {
            epoch++;
            __syncthreads();                     // all CTA threads done their writes
            if (tid == 0) {
                __threadfence();                 // publish h writes (cumulative)
                unsigned arrived = atomicAdd(&g_count, 1u);  // returns old
                if (arrived == epoch * NCTA - 1u) {
                    atomicExch(&g_epoch, epoch); // release
                } else {
                    volatile unsigned* ep = &g_epoch;
                    while (*ep < epoch) { __nanosleep(64); }
                }
                __threadfence();                 // acquire side
            }
            __syncthreads();
        }
    }
}

// -------------------- launch --------------------
extern "C" void kernel_launch(void* const* d_in, const int* in_sizes, int n_in,
                              void* d_out, int out_size) {
    const float* images   = (const float*)d_in[0];   // [256, 2048]
    const float* captions = (const float*)d_in[1];   // [256, 128, 512]
    const float* W_fc     = (const float*)d_in[2];   // [256, 2048]
    const float* b_fc     = (const float*)d_in[3];   // [256]
    const float* W_att    = (const float*)d_in[4];   // [256, 768]
    const float* b_att    = (const float*)d_in[5];   // [256]
    const float* W_ih     = (const float*)d_in[6];   // [2048, 512]
    const float* b_ih     = (const float*)d_in[7];   // [2048]
    const float* W_hh     = (const float*)d_in[8];   // [2048, 512]
    const float* b_hh     = (const float*)d_in[9];   // [2048]
    const float* W_out    = (const float*)d_in[10];  // [1004, 512]
    const float* b_out    = (const float*)d_in[11];  // [1004]
    float* out = (float*)d_out;                      // [256, 128, 1004]

    static float *p_feats = nullptr, *p_batt = nullptr, *p_bih = nullptr,
                 *p_bsum = nullptr, *p_ctx = nullptr, *p_gin = nullptr,
                 *p_hs = nullptr;
    if (!p_feats) {
        cudaGetSymbolAddress((void**)&p_feats, g_feats);
        cudaGetSymbolAddress((void**)&p_batt, g_base_att);
        cudaGetSymbolAddress((void**)&p_bih, g_base_ih);
        cudaGetSymbolAddress((void**)&p_bsum, g_bsum);
        cudaGetSymbolAddress((void**)&p_ctx, g_ctx);
        cudaGetSymbolAddress((void**)&p_gin, g_gin);
        cudaGetSymbolAddress((void**)&p_hs, g_hs);
    }
    // Idempotent; executes immediately (not a stream op) so capture-safe.
    cudaFuncSetAttribute(lstm_persistent,
                         cudaFuncAttributeMaxDynamicSharedMemorySize,
                         SM_TOTAL_BYTES);

    auto big = [&](const float* A, int lda, const float* Bw, int ldb,
                   const float* bias, const float* Cadd, int rowdiv,
                   float* C, int M, int N, int K) {
        dim3 grid((N + 127) / 128, M / 128);
        gemm_abt<128, 128, 32, 8, 8><<<grid, 256>>>(A, lda, Bw, ldb, bias, Cadd,
                                                    rowdiv, C, M, N, K);
    };
    auto small = [&](const float* A, int lda, const float* Bw, int ldb,
                     const float* bias, const float* Cadd, int rowdiv,
                     float* C, int M, int N, int K) {
        dim3 grid((N + 63) / 64, M / 64);
        gemm_abt<64, 64, 16, 4, 4><<<grid, 256>>>(A, lda, Bw, ldb, bias, Cadd,
                                                  rowdiv, C, M, N, K);
    };

    // b_ih + b_hh, and reset the grid-barrier state for this replay
    init_kernel<<<(GATES + 255) / 256, 256>>>(b_ih, b_hh, p_bsum);

    // feats = images @ W_fcᵀ + b_fc                [256,256] K=2048
    big(images, FC_IN, W_fc, FC_IN, b_fc, nullptr, 0, p_feats, BB, EMBED, FC_IN);

    // base_att = feats @ W_att[:, :256]ᵀ + b_att   [256,256] K=256
    small(p_feats, EMBED, W_att, HIDDEN + EMBED, b_att, nullptr, 0,
          p_batt, BB, EMBED, EMBED);

    // base_ih = feats @ W_ih[:, :256]ᵀ + (b_ih+b_hh)  [256,2048] K=256
    small(p_feats, EMBED, W_ih, 2 * EMBED, p_bsum, nullptr, 0,
          p_bih, BB, GATES, EMBED);

    // ctx[b*T+t] = captions[b,t] @ W_att[:, 256:]ᵀ + base_att[b]   [32768,256] K=512
    big(captions, HIDDEN, W_att + EMBED, HIDDEN + EMBED, nullptr, p_batt, TT,
        p_ctx, BB * TT, EMBED, HIDDEN);

    // gin[b*T+t] = ctx[b*T+t] @ W_ih[:, 256:]ᵀ + base_ih[b]        [32768,2048] K=256
    big(p_ctx, EMBED, W_ih + EMBED, 2 * EMBED, nullptr, p_bih, TT,
        p_gin, BB * TT, GATES, EMBED);

    // full recurrence in ONE persistent kernel
    lstm_persistent<<<NCTA, 256, SM_TOTAL_BYTES>>>(W_hh, p_gin, p_hs);

    // out = hs @ W_outᵀ + b_out     [32768,1004] K=512
    big(p_hs, HIDDEN, W_out, HIDDEN, b_out, nullptr, 0,
        out, BB * TT, VOCAB, HIDDEN);
}

// round 5
// speedup vs baseline: 2.3195x; 1.3168x over previous
#include <cuda_runtime.h>
#include <cstdint>
#include <math.h>

// Problem constants
#define BB 256      // batch
#define TT 128      // time steps
#define EMBED 256
#define HIDDEN 512
#define VOCAB 1004
#define FC_IN 2048
#define GATES 2048  // 4*HIDDEN

#define NCTA 128    // persistent recurrence grid

// ==================== helpers ====================
__device__ __forceinline__ uint32_t smem_u32(const void* p) {
    uint32_t a;
    asm("{ .reg .u64 t; cvta.to.shared.u64 t, %1; cvt.u32.u64 %0, t; }"
        : "=r"(a) : "l"(p));
    return a;
}

// Split 2 fp32 -> bf16x2 hi + bf16x2 lo (low 16 bits = first element)
__device__ __forceinline__ void split2(float x, float y, uint32_t& hi, uint32_t& lo) {
    uint32_t h;
    asm("cvt.rn.bf16x2.f32 %0, %1, %2;" : "=r"(h) : "f"(y), "f"(x));
    float fx = __uint_as_float(h << 16);
    float fy = __uint_as_float(h & 0xFFFF0000u);
    float rx = x - fx, ry = y - fy;
    uint32_t l;
    asm("cvt.rn.bf16x2.f32 %0, %1, %2;" : "=r"(l) : "f"(ry), "f"(rx));
    hi = h; lo = l;
}

__device__ __forceinline__ void ldsm4(uint32_t addr, uint32_t r[4]) {
    asm volatile("ldmatrix.sync.aligned.m8n8.x4.shared.b16 {%0,%1,%2,%3}, [%4];"
                 : "=r"(r[0]), "=r"(r[1]), "=r"(r[2]), "=r"(r[3]) : "r"(addr));
}

__device__ __forceinline__ void mma16816(float d[4], const uint32_t a[4],
                                         const uint32_t b[2]) {
    asm volatile(
        "mma.sync.aligned.m16n8k16.row.col.f32.bf16.bf16.f32 "
        "{%0,%1,%2,%3}, {%4,%5,%6,%7}, {%8,%9}, {%0,%1,%2,%3};"
        : "+f"(d[0]), "+f"(d[1]), "+f"(d[2]), "+f"(d[3])
        : "r"(a[0]), "r"(a[1]), "r"(a[2]), "r"(a[3]), "r"(b[0]), "r"(b[1]));
}

// ==================== device scratch ====================
__device__ float g_feats[BB * EMBED];
__device__ float g_base_att[BB * EMBED];
__device__ float g_base_ih[BB * GATES];
__device__ float g_bsum[GATES];
__device__ float g_ctx[(size_t)BB * TT * EMBED];
__device__ float g_gin[(size_t)BB * TT * GATES];
__device__ float g_hs[(size_t)BB * TT * HIDDEN];
__device__ float g_hbuf[2][BB][HIDDEN];
__device__ unsigned g_count;
__device__ unsigned g_epoch;

// ==================== HMMA bf16x3 GEMM: C = A @ Bw^T ====================
// A: [M,K] row-major (lda), Bw: [N,K] row-major (ldb), fp32 in/out.
// Requires M % BM == 0, K % 32 == 0, lda/ldb % 4 == 0. N arbitrary (guarded).
// 8 warps: 2 (m) x 4 (n). Warp tile WM x WN. 3 MMA passes: hi*hi + hi*lo + lo*hi.
template <int BM, int BN>
__global__ void __launch_bounds__(256, 1)
gemm_hmma(const float* __restrict__ A, int lda,
          const float* __restrict__ Bw, int ldb,
          const float* __restrict__ bias,
          const float* __restrict__ Cadd, int rowdiv,
          float* __restrict__ C,
          int M, int N, int K) {
    constexpr int WM = BM / 2;
    constexpr int WN = BN / 4;
    constexpr int MI = WM / 16;
    constexpr int NI = WN / 8;
    constexpr int LDS = 40;  // bf16 row stride (80 B): conflict-free ldmatrix

    __shared__ __align__(16) uint16_t As_hi[BM * LDS];
    __shared__ __align__(16) uint16_t As_lo[BM * LDS];
    __shared__ __align__(16) uint16_t Bs_hi[BN * LDS];
    __shared__ __align__(16) uint16_t Bs_lo[BN * LDS];

    const int tid = threadIdx.x;
    const int lane = tid & 31;
    const int wid = tid >> 5;
    const int warp_m = wid >> 2;
    const int warp_n = wid & 3;
    const int bm = blockIdx.y * BM;
    const int bn = blockIdx.x * BN;

    const uint32_t sAhi = smem_u32(As_hi), sAlo = smem_u32(As_lo);
    const uint32_t sBhi = smem_u32(Bs_hi), sBlo = smem_u32(Bs_lo);

    float acc[MI][NI][4];
#pragma unroll
    for (int mi = 0; mi < MI; mi++)
#pragma unroll
        for (int ni = 0; ni < NI; ni++)
#pragma unroll
            for (int e = 0; e < 4; e++) acc[mi][ni][e] = 0.f;

    // ldmatrix per-lane addressing
    const int a_r = lane & 15;
    const int a_c = (lane >> 4) << 3;          // 0 or 8 (k offset)
    const int b_r = lane & 7;
    const int b_c = ((lane >> 3) & 1) << 3;    // 0 or 8 (k offset)
    const int b_m = (lane >> 4) & 1;           // which n8 block of the pair

    for (int kt = 0; kt < K; kt += 32) {
        __syncthreads();  // previous iteration's reads done before overwrite

        // ---- load + split A tile [BM rows x 32 k] ----
#pragma unroll
        for (int i = 0; i < BM / 32; i++) {
            int f = tid + i * 256;     // float4 id over [BM][8]
            int row = f >> 3;
            int q = f & 7;
            float4 v = *(const float4*)(A + (size_t)(bm + row) * lda + kt + q * 4);
            uint32_t h01, l01, h23, l23;
            split2(v.x, v.y, h01, l01);
            split2(v.z, v.w, h23, l23);
            uint32_t off = (uint32_t)(row * LDS + q * 4) * 2;
            asm volatile("st.shared.v2.b32 [%0], {%1, %2};"
                         :: "r"(sAhi + off), "r"(h01), "r"(h23) : "memory");
            asm volatile("st.shared.v2.b32 [%0], {%1, %2};"
                         :: "r"(sAlo + off), "r"(l01), "r"(l23) : "memory");
        }
        // ---- load + split B tile [BN n-rows x 32 k], guard n < N ----
#pragma unroll
        for (int i = 0; i < BN / 32; i++) {
            int f = tid + i * 256;
            int row = f >> 3;
            int q = f & 7;
            float4 v = make_float4(0.f, 0.f, 0.f, 0.f);
            int gn = bn + row;
            if (gn < N) v = *(const float4*)(Bw + (size_t)gn * ldb + kt + q * 4);
            uint32_t h01, l01, h23, l23;
            split2(v.x, v.y, h01, l01);
            split2(v.z, v.w, h23, l23);
            uint32_t off = (uint32_t)(row * LDS + q * 4) * 2;
            asm volatile("st.shared.v2.b32 [%0], {%1, %2};"
                         :: "r"(sBhi + off), "r"(h01), "r"(h23) : "memory");
            asm volatile("st.shared.v2.b32 [%0], {%1, %2};"
                         :: "r"(sBlo + off), "r"(l01), "r"(l23) : "memory");
        }
        __syncthreads();

        // ---- compute: 2 k-steps of 16 ----
#pragma unroll
        for (int ks = 0; ks < 2; ks++) {
            const int k0 = ks * 16;

            uint32_t ah[MI][4], al[MI][4];
#pragma unroll
            for (int mi = 0; mi < MI; mi++) {
                uint32_t off =
                    (uint32_t)((warp_m * WM + mi * 16 + a_r) * LDS + k0 + a_c) * 2;
                ldsm4(sAhi + off, ah[mi]);
                ldsm4(sAlo + off, al[mi]);
            }
            uint32_t bh[NI][2], bl[NI][2];
#pragma unroll
            for (int p = 0; p < NI / 2; p++) {
                uint32_t off =
                    (uint32_t)((warp_n * WN + (p * 2 + b_m) * 8 + b_r) * LDS +
                               k0 + b_c) * 2;
                uint32_t r4[4];
                ldsm4(sBhi + off, r4);
                bh[2 * p][0] = r4[0]; bh[2 * p][1] = r4[1];
                bh[2 * p + 1][0] = r4[2]; bh[2 * p + 1][1] = r4[3];
                ldsm4(sBlo + off, r4);
                bl[2 * p][0] = r4[0]; bl[2 * p][1] = r4[1];
                bl[2 * p + 1][0] = r4[2]; bl[2 * p + 1][1] = r4[3];
            }
#pragma unroll
            for (int mi = 0; mi < MI; mi++)
#pragma unroll
                for (int ni = 0; ni < NI; ni++) {
                    mma16816(acc[mi][ni], ah[mi], bh[ni]);
                    mma16816(acc[mi][ni], ah[mi], bl[ni]);
                    mma16816(acc[mi][ni], al[mi], bh[ni]);
                }
        }
    }

    // ---- epilogue: frag -> gmem with fused bias / row-broadcast Cadd ----
#pragma unroll
    for (int mi = 0; mi < MI; mi++) {
        int gm0 = bm + warp_m * WM + mi * 16 + (lane >> 2);
        int gm1 = gm0 + 8;
        const float* cr0 = Cadd
            ? Cadd + (size_t)(rowdiv > 1 ? gm0 / rowdiv : gm0) * N : (const float*)0;
        const float* cr1 = Cadd
            ? Cadd + (size_t)(rowdiv > 1 ? gm1 / rowdiv : gm1) * N : (const float*)0;
#pragma unroll
        for (int ni = 0; ni < NI; ni++) {
            int gn = bn + warp_n * WN + ni * 8 + (lane & 3) * 2;
            if (gn + 1 < N) {
                float b0 = bias ? bias[gn] : 0.f;
                float b1 = bias ? bias[gn + 1] : 0.f;
                float2 v0, v1;
                v0.x = acc[mi][ni][0] + b0 + (cr0 ? cr0[gn] : 0.f);
                v0.y = acc[mi][ni][1] + b1 + (cr0 ? cr0[gn + 1] : 0.f);
                v1.x = acc[mi][ni][2] + b0 + (cr1 ? cr1[gn] : 0.f);
                v1.y = acc[mi][ni][3] + b1 + (cr1 ? cr1[gn + 1] : 0.f);
                *(float2*)(C + (size_t)gm0 * N + gn) = v0;
                *(float2*)(C + (size_t)gm1 * N + gn) = v1;
            } else if (gn < N) {
                float b0 = bias ? bias[gn] : 0.f;
                C[(size_t)gm0 * N + gn] = acc[mi][ni][0] + b0 + (cr0 ? cr0[gn] : 0.f);
                C[(size_t)gm1 * N + gn] = acc[mi][ni][2] + b0 + (cr1 ? cr1[gn] : 0.f);
            }
        }
    }
}

// ==================== init kernel: bias sum + barrier reset ====================
__global__ void init_kernel(const float* __restrict__ b_ih,
                            const float* __restrict__ b_hh,
                            float* __restrict__ bsum) {
    int n = blockIdx.x * blockDim.x + threadIdx.x;
    if (n < GATES) bsum[n] = b_ih[n] + b_hh[n];
    if (n == 0) { g_count = 0u; g_epoch = 0u; }
}

__device__ __forceinline__ float sigmoidf_(float x) {
    return 1.f / (1.f + expf(-x));
}

// ==================== persistent recurrence kernel (unchanged) ====================
#define SM_WS   (512 * 36)
#define SM_HS   (16 * 128)
#define SM_GS   (128 * 33)
#define SM_CS   (128 * 8)
#define SM_TOTAL_BYTES ((SM_WS + SM_HS + SM_GS + SM_CS) * 4)

__global__ void __launch_bounds__(256, 1)
lstm_persistent(const float* __restrict__ W_hh,   // [2048,512]
                const float* __restrict__ gin,    // [B,T,2048]
                float* __restrict__ hs)           // [B,T,512]
{
    extern __shared__ float sm[];
    float* Ws = sm;
    float* Hs = Ws + SM_WS;
    float* Gs = Hs + SM_HS;
    float* Cs = Gs + SM_GS;

    const int tid = threadIdx.x;
    const int bid = blockIdx.x;
    const int bbase = (bid & 1) * 128;
    const int jbase = (bid >> 1) * 8;

    for (int idx = tid; idx < 32 * 512; idx += 256) {
        int c = idx >> 9;
        int k = idx & 511;
        int gcol = (c >> 3) * 512 + jbase + (c & 7);
        Ws[k * 36 + c] = W_hh[(size_t)gcol * HIDDEN + k];
    }
    __syncthreads();

    const int trow = tid >> 3;
    const int tcol = tid & 7;

    unsigned epoch = 0;

    for (int t = 0; t < TT; t++) {
        float acc[4][4];
#pragma unroll
        for (int i = 0; i < 4; i++)
#pragma unroll
            for (int j = 0; j < 4; j++) acc[i][j] = 0.f;

        if (t > 0) {
            const float* hsrc = &g_hbuf[(t - 1) & 1][bbase][0];
            for (int kt = 0; kt < HIDDEN; kt += 16) {
#pragma unroll
                for (int s = 0; s < 2; s++) {
                    int idx = tid * 2 + s;
                    int r = idx >> 2;
                    int q = idx & 3;
                    float4 v = *(const float4*)(hsrc + (size_t)r * HIDDEN + kt + q * 4);
                    Hs[(q * 4 + 0) * 128 + r] = v.x;
                    Hs[(q * 4 + 1) * 128 + r] = v.y;
                    Hs[(q * 4 + 2) * 128 + r] = v.z;
                    Hs[(q * 4 + 3) * 128 + r] = v.w;
                }
                __syncthreads();
#pragma unroll
                for (int k = 0; k < 16; k++) {
                    float4 m = *(const float4*)(Hs + k * 128 + trow * 4);
                    float4 n = *(const float4*)(Ws + (kt + k) * 36 + tcol * 4);
                    float rm[4] = {m.x, m.y, m.z, m.w};
                    float rn[4] = {n.x, n.y, n.z, n.w};
#pragma unroll
                    for (int i = 0; i < 4; i++)
#pragma unroll
                        for (int j = 0; j < 4; j++) acc[i][j] += rm[i] * rn[j];
                }
                __syncthreads();
            }
        }

        {
            int c0 = tcol * 4;
            int gate = c0 >> 3;
            int jj0 = c0 & 7;
#pragma unroll
            for (int i = 0; i < 4; i++) {
                int bl = trow * 4 + i;
                const float* grow_p =
                    gin + ((size_t)(bbase + bl) * TT + t) * GATES + gate * 512 + jbase + jj0;
                float4 g4 = *(const float4*)grow_p;
                Gs[bl * 33 + c0 + 0] = acc[i][0] + g4.x;
                Gs[bl * 33 + c0 + 1] = acc[i][1] + g4.y;
                Gs[bl * 33 + c0 + 2] = acc[i][2] + g4.z;
                Gs[bl * 33 + c0 + 3] = acc[i][3] + g4.w;
            }
        }
        __syncthreads();

#pragma unroll
        for (int s = 0; s < 4; s++) {
            int q = tid * 4 + s;
            int bl = q >> 3;
            int jj = q & 7;
            float gi = Gs[bl * 33 + jj];
            float gf = Gs[bl * 33 + 8 + jj];
            float gg = Gs[bl * 33 + 16 + jj];
            float go = Gs[bl * 33 + 24 + jj];
            float cprev = (t == 0) ? 0.f : Cs[bl * 8 + jj];
            float cc = sigmoidf_(gf) * cprev + sigmoidf_(gi) * tanhf(gg);
            float hh = sigmoidf_(go) * tanhf(cc);
            Cs[bl * 8 + jj] = cc;
            g_hbuf[t & 1][bbase + bl][jbase + jj] = hh;
            hs[((size_t)(bbase + bl) * TT + t) * HIDDEN + jbase + jj] = hh;
        }

        if (t < TT - 1) {
            epoch++;
            __syncthreads();
            if (tid == 0) {
                __threadfence();
                unsigned arrived = atomicAdd(&g_count, 1u);
                if (arrived == epoch * NCTA - 1u) {
                    atomicExch(&g_epoch, epoch);
                } else {
                    volatile unsigned* ep = &g_epoch;
                    while (*ep < epoch) { __nanosleep(64); }
                }
                __threadfence();
            }
            __syncthreads();
        }
    }
}

// ==================== launch ====================
extern "C" void kernel_launch(void* const* d_in, const int* in_sizes, int n_in,
                              void* d_out, int out_size) {
    const float* images   = (const float*)d_in[0];   // [256, 2048]
    const float* captions = (const float*)d_in[1];   // [256, 128, 512]
    const float* W_fc     = (const float*)d_in[2];   // [256, 2048]
    const float* b_fc     = (const float*)d_in[3];   // [256]
    const float* W_att    = (const float*)d_in[4];   // [256, 768]
    const float* b_att    = (const float*)d_in[5];   // [256]
    const float* W_ih     = (const float*)d_in[6];   // [2048, 512]
    const float* b_ih     = (const float*)d_in[7];   // [2048]
    const float* W_hh     = (const float*)d_in[8];   // [2048, 512]
    const float* b_hh     = (const float*)d_in[9];   // [2048]
    const float* W_out    = (const float*)d_in[10];  // [1004, 512]
    const float* b_out    = (const float*)d_in[11];  // [1004]
    float* out = (float*)d_out;                      // [256, 128, 1004]

    static float *p_feats = nullptr, *p_batt = nullptr, *p_bih = nullptr,
                 *p_bsum = nullptr, *p_ctx = nullptr, *p_gin = nullptr,
                 *p_hs = nullptr;
    if (!p_feats) {
        cudaGetSymbolAddress((void**)&p_feats, g_feats);
        cudaGetSymbolAddress((void**)&p_batt, g_base_att);
        cudaGetSymbolAddress((void**)&p_bih, g_base_ih);
        cudaGetSymbolAddress((void**)&p_bsum, g_bsum);
        cudaGetSymbolAddress((void**)&p_ctx, g_ctx);
        cudaGetSymbolAddress((void**)&p_gin, g_gin);
        cudaGetSymbolAddress((void**)&p_hs, g_hs);
        cudaFuncSetAttribute(lstm_persistent,
                             cudaFuncAttributeMaxDynamicSharedMemorySize,
                             SM_TOTAL_BYTES);
    }

    auto tc = [&](const float* A, int lda, const float* Bw, int ldb,
                  const float* bias, const float* Cadd, int rowdiv,
                  float* C, int M, int N, int K) {
        dim3 grid((N + 127) / 128, M / 128);
        gemm_hmma<128, 128><<<grid, 256>>>(A, lda, Bw, ldb, bias, Cadd,
                                           rowdiv, C, M, N, K);
    };
    auto tcs = [&](const float* A, int lda, const float* Bw, int ldb,
                   const float* bias, const float* Cadd, int rowdiv,
                   float* C, int M, int N, int K) {
        dim3 grid((N + 63) / 64, M / 64);
        gemm_hmma<64, 64><<<grid, 256>>>(A, lda, Bw, ldb, bias, Cadd,
                                         rowdiv, C, M, N, K);
    };

    // b_ih + b_hh, and reset the grid-barrier state for this replay
    init_kernel<<<(GATES + 255) / 256, 256>>>(b_ih, b_hh, p_bsum);

    // feats = images @ W_fcᵀ + b_fc                [256,256] K=2048
    tcs(images, FC_IN, W_fc, FC_IN, b_fc, nullptr, 0, p_feats, BB, EMBED, FC_IN);

    // base_att = feats @ W_att[:, :256]ᵀ + b_att   [256,256] K=256
    tcs(p_feats, EMBED, W_att, HIDDEN + EMBED, b_att, nullptr, 0,
        p_batt, BB, EMBED, EMBED);

    // base_ih = feats @ W_ih[:, :256]ᵀ + (b_ih+b_hh)  [256,2048] K=256
    tcs(p_feats, EMBED, W_ih, 2 * EMBED, p_bsum, nullptr, 0,
        p_bih, BB, GATES, EMBED);

    // ctx[b*T+t] = captions[b,t] @ W_att[:, 256:]ᵀ + base_att[b]   [32768,256] K=512
    tc(captions, HIDDEN, W_att + EMBED, HIDDEN + EMBED, nullptr, p_batt, TT,
       p_ctx, BB * TT, EMBED, HIDDEN);

    // gin[b*T+t] = ctx[b*T+t] @ W_ih[:, 256:]ᵀ + base_ih[b]        [32768,2048] K=256
    tc(p_ctx, EMBED, W_ih + EMBED, 2 * EMBED, nullptr, p_bih, TT,
       p_gin, BB * TT, GATES, EMBED);

    // full recurrence in ONE persistent kernel
    lstm_persistent<<<NCTA, 256, SM_TOTAL_BYTES>>>(W_hh, p_gin, p_hs);

    // out = hs @ W_outᵀ + b_out     [32768,1004] K=512
    tc(p_hs, HIDDEN, W_out, HIDDEN, b_out, nullptr, 0,
       out, BB * TT, VOCAB, HIDDEN);
}